// round 8
// baseline (speedup 1.0000x reference)
#include <cuda_runtime.h>
#include <cuda_fp16.h>
#include <cuda_bf16.h>

// ---------------------------------------------------------------------------
// NonlocalBlock: B=4, C=64, N=9216, Ci=32, M=4608
// Round 8: 128-row blocks with 8 thin warps (16 rows each) -> 25% occupancy
// with R7's staging amortization. fp16 tensor attn, f32x2 proj/epilogue.
// ---------------------------------------------------------------------------

#define BB 4
#define CC 64
#define NN 9216
#define CI 32
#define MM 4608
#define TILES (MM / 64)
#define LOG2E 1.4426950408889634f

typedef unsigned long long ull;

// scratch (__device__ globals: allocation-free rule)
__device__ __half d_thH[(size_t)BB * NN * CI];   // theta*log2e hi (fp16)
__device__ __half d_thL[(size_t)BB * NN * CI];   // theta*log2e lo (fp16)
__device__ __half d_ph [(size_t)BB * MM * CI];   // phi (fp16 rn)
__device__ __half d_gT [(size_t)BB * CI * MM];   // g transposed (fp16 rn)

// ---- f32x2 helpers --------------------------------------------------------
__device__ __forceinline__ ull pk2(float lo, float hi) {
    ull r; asm("mov.b64 %0, {%1,%2};" : "=l"(r) : "f"(lo), "f"(hi)); return r;
}
__device__ __forceinline__ void upk2(ull a, float& lo, float& hi) {
    asm("mov.b64 {%0,%1}, %2;" : "=f"(lo), "=f"(hi) : "l"(a));
}
__device__ __forceinline__ ull fma2(ull a, ull b, ull c) {
    ull d; asm("fma.rn.f32x2 %0, %1, %2, %3;" : "=l"(d) : "l"(a), "l"(b), "l"(c)); return d;
}

// ---- fp16 mma helpers -----------------------------------------------------
__device__ __forceinline__ void mma16(float* c, const unsigned* a,
                                      unsigned b0, unsigned b1) {
    asm volatile(
        "mma.sync.aligned.m16n8k16.row.col.f32.f16.f16.f32 "
        "{%0,%1,%2,%3}, {%4,%5,%6,%7}, {%8,%9}, {%0,%1,%2,%3};"
        : "+f"(c[0]), "+f"(c[1]), "+f"(c[2]), "+f"(c[3])
        : "r"(a[0]), "r"(a[1]), "r"(a[2]), "r"(a[3]), "r"(b0), "r"(b1));
}
__device__ __forceinline__ void mma16z(float* d, const unsigned* a,
                                       unsigned b0, unsigned b1) {
    asm volatile(
        "mma.sync.aligned.m16n8k16.row.col.f32.f16.f16.f32 "
        "{%0,%1,%2,%3}, {%4,%5,%6,%7}, {%8,%9}, {%10,%11,%12,%13};"
        : "=f"(d[0]), "=f"(d[1]), "=f"(d[2]), "=f"(d[3])
        : "r"(a[0]), "r"(a[1]), "r"(a[2]), "r"(a[3]), "r"(b0), "r"(b1),
          "f"(0.f), "f"(0.f), "f"(0.f), "f"(0.f));
}
__device__ __forceinline__ uint4 ldsm4(unsigned a) {
    uint4 r;
    asm volatile("ldmatrix.sync.aligned.m8n8.x4.shared.b16 {%0,%1,%2,%3}, [%4];"
                 : "=r"(r.x), "=r"(r.y), "=r"(r.z), "=r"(r.w) : "r"(a));
    return r;
}
__device__ __forceinline__ void cpa16(unsigned s, const void* g) {
    asm volatile("cp.async.ca.shared.global [%0], [%1], 16;" :: "r"(s), "l"(g));
}
__device__ __forceinline__ void cpcommit() { asm volatile("cp.async.commit_group;"); }
template <int N> __device__ __forceinline__ void cpwait() {
    asm volatile("cp.async.wait_group %0;" :: "n"(N));
}
__device__ __forceinline__ unsigned pkhf2(float lo, float hi) {
    unsigned d; asm("cvt.rn.f16x2.f32 %0, %1, %2;" : "=r"(d) : "f"(hi), "f"(lo));
    return d;
}
__device__ __forceinline__ unsigned h2ex2(unsigned x) {
    unsigned d; asm("ex2.approx.f16x2 %0, %1;" : "=r"(d) : "r"(x));
    return d;
}

// ---------------------------------------------------------------------------
// Kernel 1: projections + maxpool, f32x2-packed math.
// grid = (NN/64, BB), 256 threads (8 groups of 8 positions; lane = ci).
// ---------------------------------------------------------------------------
__global__ __launch_bounds__(256, 2)
void proj_kernel(const float* __restrict__ x,
                 const float* __restrict__ wt, const float* __restrict__ bt,
                 const float* __restrict__ wp, const float* __restrict__ bp,
                 const float* __restrict__ wg, const float* __restrict__ bg)
{
    __shared__ float xs[64][66];          // [chan][pos], conflict-free
    __shared__ float wts[64][32];
    __shared__ float wps[64][32];
    __shared__ float wgs[64][32];
    __shared__ __half gs[32][36];         // pooled g transpose buffer

    const int b  = blockIdx.y;
    const int n0 = blockIdx.x * 64;
    const int tid = threadIdx.x;

    for (int i = tid; i < CI * CC; i += 256) {
        int ci = i >> 6, c = i & 63;
        wts[c][ci] = wt[i];
        wps[c][ci] = wp[i];
        wgs[c][ci] = wg[i];
    }
    for (int i = tid; i < 64 * 64; i += 256) {
        int c = i >> 6, nl = i & 63;
        xs[c][nl] = x[((size_t)(b * CC + c)) * NN + n0 + nl];
    }
    __syncthreads();

    const int ci = tid & 31;
    const int g8 = tid >> 5;
    const int p0 = g8 * 8;

    ull at2[4], ap2[4], ag2[4];
    #pragma unroll
    for (int j = 0; j < 4; ++j) { at2[j] = 0ull; ap2[j] = 0ull; ag2[j] = 0ull; }

    #pragma unroll
    for (int cb = 0; cb < 64; cb += 8) {
        ull wt2[8], wp2[8], wg2[8];
        #pragma unroll
        for (int k = 0; k < 8; ++k) {
            float a = wts[cb + k][ci]; wt2[k] = pk2(a, a);
            float p = wps[cb + k][ci]; wp2[k] = pk2(p, p);
            float g = wgs[cb + k][ci]; wg2[k] = pk2(g, g);
        }
        #pragma unroll
        for (int k = 0; k < 8; ++k) {
            #pragma unroll
            for (int j = 0; j < 4; ++j) {
                ull xv = *(const ull*)&xs[cb + k][p0 + 2 * j];
                at2[j] = fma2(xv, wt2[k], at2[j]);
                ap2[j] = fma2(xv, wp2[k], ap2[j]);
                ag2[j] = fma2(xv, wg2[k], ag2[j]);
            }
        }
    }

    const float bth = bt[ci], bph = bp[ci], bgg = bg[ci];
    #pragma unroll
    for (int j = 0; j < 4; ++j) {
        const int n = n0 + p0 + 2 * j;
        float alo, ahi; upk2(at2[j], alo, ahi);
        const float tv0 = (alo + bth) * LOG2E;
        const float tv1 = (ahi + bth) * LOG2E;
        {
            const size_t t0 = ((size_t)(b * NN + n)) * CI + ci;
            __half h0 = __float2half_rn(tv0);
            d_thH[t0] = h0;
            d_thL[t0] = __float2half_rn(tv0 - __half2float(h0));
            __half h1 = __float2half_rn(tv1);
            d_thH[t0 + CI] = h1;
            d_thL[t0 + CI] = __float2half_rn(tv1 - __half2float(h1));
        }
        float plo, phi_; upk2(ap2[j], plo, phi_);
        const float pv = fmaxf(plo, phi_) + bph;
        const int m = n >> 1;
        d_ph[((size_t)(b * MM + m)) * CI + ci] = __float2half_rn(pv);
        float glo, ghi; upk2(ag2[j], glo, ghi);
        gs[ci][g8 * 4 + j] = __float2half_rn(fmaxf(glo, ghi) + bgg);
    }
    __syncthreads();

    // coalesced gT write: 32 ci rows x 32 m (64B per row)
    for (int i = tid; i < 32 * 32; i += 256) {
        const int cr = i >> 5, ml = i & 31;
        d_gT[((size_t)(b * CI + cr)) * MM + (n0 >> 1) + ml] = gs[cr][ml];
    }
}

// ---------------------------------------------------------------------------
// smem byte offsets
// ---------------------------------------------------------------------------
#define PH0o 0u           // phi buf0: 64 keys x 80B rows = 5120
#define PH1o 5120u
#define G0o  10240u       // gT buf0: 32 ci x 144B rows = 4608
#define G1o  14848u
#define WOo  19456u       // paired w_out: 32 pairs x 33 x float2 = 8448
#define SMSZ 27904u

// ---------------------------------------------------------------------------
// Kernel 2: flash attention + out-proj + residual.
// grid = (NN/128, BB), 256 threads (8 warps x 16 query rows).
// ---------------------------------------------------------------------------
__global__ __launch_bounds__(256, 2)
void attn_kernel(const float* __restrict__ x,
                 const float* __restrict__ w_out,
                 const float* __restrict__ b_out,
                 float* __restrict__ out)
{
    __shared__ __align__(16) unsigned char SM[SMSZ];
    const unsigned shb = (unsigned)__cvta_generic_to_shared(SM);

    const int b    = blockIdx.y;
    const int n0b  = blockIdx.x * 128;
    const int tid  = threadIdx.x;
    const int warp = tid >> 5;
    const int lane = tid & 31;
    const int grp  = lane >> 2;
    const int t    = lane & 3;

    // w_out in channel-paired layout for f32x2 epilogue
    {
        float* woF = (float*)(SM + WOo);
        for (int i = tid; i < CC * CI; i += 256) {
            int c = i >> 5, ci = i & 31;
            woF[((c >> 1) * 33 + ci) * 2 + (c & 1)] = w_out[i];
        }
    }

    // ---- theta A fragments (fp16 hi/lo) ---------------------------------
    const int row0 = warp * 16 + grp;      // local rows row0, row0+8
    unsigned aH[2][4], aL[2][4];
    {
        const __half* thH = d_thH + ((size_t)(b * NN + n0b)) * CI;
        const __half* thL = d_thL + ((size_t)(b * NN + n0b)) * CI;
        #pragma unroll
        for (int ch = 0; ch < 2; ++ch) {
            const int c0 = ch * 16 + 2 * t;
            aH[ch][0] = *(const unsigned*)(thH + (size_t)row0 * CI + c0);
            aH[ch][1] = *(const unsigned*)(thH + (size_t)(row0 + 8) * CI + c0);
            aH[ch][2] = *(const unsigned*)(thH + (size_t)row0 * CI + c0 + 8);
            aH[ch][3] = *(const unsigned*)(thH + (size_t)(row0 + 8) * CI + c0 + 8);
            aL[ch][0] = *(const unsigned*)(thL + (size_t)row0 * CI + c0);
            aL[ch][1] = *(const unsigned*)(thL + (size_t)(row0 + 8) * CI + c0);
            aL[ch][2] = *(const unsigned*)(thL + (size_t)row0 * CI + c0 + 8);
            aL[ch][3] = *(const unsigned*)(thL + (size_t)(row0 + 8) * CI + c0 + 8);
        }
    }

    float y[4][4];
    #pragma unroll
    for (int i = 0; i < 4; ++i)
        #pragma unroll
        for (int j = 0; j < 4; ++j) y[i][j] = 0.f;
    float y5[4] = {0.f, 0.f, 0.f, 0.f};
    float rm0 = -1e30f, rm1 = -1e30f;

    const unsigned onesB = (grp == 0) ? 0x3C003C00u : 0u;

    const char* gph = (const char*)(d_ph + ((size_t)b * MM) * CI);
    const char* ggT = (const char*)(d_gT + (size_t)b * CI * MM);

    auto copy_tile = [&](int mt, int buf) {
        const unsigned phO = buf ? PH1o : PH0o;
        const unsigned gO  = buf ? G1o : G0o;
        const char* ph = gph + (size_t)mt * 64 * CI * 2;
        {   // phi: 256 x 16B chunks, one per thread
            int key = tid >> 2, c = tid & 3;
            cpa16(shb + phO + key * 80 + c * 16, ph + tid * 16);
        }
        {   // gT: 256 x 16B chunks, one per thread
            int ci = tid >> 3, c = tid & 7;
            cpa16(shb + gO + ci * 144 + c * 16,
                  ggT + (size_t)ci * (MM * 2) + (size_t)mt * 128 + c * 16);
        }
    };

    copy_tile(0, 0);
    cpcommit();

    const unsigned lmBase = (lane & 7) * 80 + (lane >> 3) * 16;   // phi ldsm
    const unsigned lmG = (unsigned)(((lane >> 4) * 8 + (lane & 7)) * 144 +
                                    ((lane >> 3) & 1) * 16);

    for (int mt = 0; mt < TILES; ++mt) {
        const int cur = mt & 1;
        if (mt + 1 < TILES) { copy_tile(mt + 1, cur ^ 1); cpcommit(); cpwait<1>(); }
        else                { cpwait<0>(); }
        __syncthreads();

        const unsigned phA = shb + (cur ? PH1o : PH0o) + lmBase;
        const unsigned gA  = shb + (cur ? G1o : G0o) + lmG;

        // ---- S = (thH + thL) . phi^T  (2 terms, zero-C first mma) -------
        float s[8][4];
        #pragma unroll
        for (int nt = 0; nt < 8; ++nt) {
            uint4 bh = ldsm4(phA + nt * 640);
            mma16z(s[nt], aH[0], bh.x, bh.y);
            mma16(s[nt], aH[1], bh.z, bh.w);
            mma16(s[nt], aL[0], bh.x, bh.y);
            mma16(s[nt], aL[1], bh.z, bh.w);
        }

        // ---- online softmax (log2 domain) -------------------------------
        float m0 = s[0][0], m1 = s[0][2];
        #pragma unroll
        for (int nt = 0; nt < 8; ++nt) {
            m0 = fmaxf(m0, fmaxf(s[nt][0], s[nt][1]));
            m1 = fmaxf(m1, fmaxf(s[nt][2], s[nt][3]));
        }
        m0 = fmaxf(m0, __shfl_xor_sync(0xffffffffu, m0, 1));
        m0 = fmaxf(m0, __shfl_xor_sync(0xffffffffu, m0, 2));
        m1 = fmaxf(m1, __shfl_xor_sync(0xffffffffu, m1, 1));
        m1 = fmaxf(m1, __shfl_xor_sync(0xffffffffu, m1, 2));

        const float nm0 = fmaxf(rm0, m0);
        const float nm1 = fmaxf(rm1, m1);
        const float sc0 = exp2f(rm0 - nm0);
        const float sc1 = exp2f(rm1 - nm1);
        rm0 = nm0; rm1 = nm1;
        #pragma unroll
        for (int nc = 0; nc < 4; ++nc) {
            y[nc][0] *= sc0; y[nc][1] *= sc0;
            y[nc][2] *= sc1; y[nc][3] *= sc1;
        }
        y5[0] *= sc0; y5[2] *= sc1;

        // ---- P = 2^(S-m) via f16x2 MUFU;  y += P @ g; y5 += P @ ones ----
        #pragma unroll
        for (int kc = 0; kc < 4; ++kc) {
            const int nt0 = 2 * kc, nt1 = 2 * kc + 1;
            unsigned pa[4];
            pa[0] = h2ex2(pkhf2(s[nt0][0] - nm0, s[nt0][1] - nm0));
            pa[1] = h2ex2(pkhf2(s[nt0][2] - nm1, s[nt0][3] - nm1));
            pa[2] = h2ex2(pkhf2(s[nt1][0] - nm0, s[nt1][1] - nm0));
            pa[3] = h2ex2(pkhf2(s[nt1][2] - nm1, s[nt1][3] - nm1));

            uint4 h0 = ldsm4(gA + kc * 32);            // nc 0,1
            uint4 h1 = ldsm4(gA + 2304 + kc * 32);     // nc 2,3
            mma16(y[0], pa, h0.x, h0.y);
            mma16(y[1], pa, h0.z, h0.w);
            mma16(y[2], pa, h1.x, h1.y);
            mma16(y[3], pa, h1.z, h1.w);
            mma16(y5,   pa, onesB, onesB);
        }
        __syncthreads();
    }

    // row sums live in col 0 (t==0 lanes): broadcast within each group
    const float rs0 = __shfl_sync(0xffffffffu, y5[0], lane & ~3);
    const float rs1 = __shfl_sync(0xffffffffu, y5[2], lane & ~3);
    const float inv0 = 1.0f / rs0;
    const float inv1 = 1.0f / rs1;

    float* ySm = (float*)SM;               // 128 x 33 floats = 16896 B < WOo
    #pragma unroll
    for (int nc = 0; nc < 4; ++nc) {
        ySm[row0 * 33 + nc * 8 + 2 * t]           = y[nc][0] * inv0;
        ySm[row0 * 33 + nc * 8 + 2 * t + 1]       = y[nc][1] * inv0;
        ySm[(row0 + 8) * 33 + nc * 8 + 2 * t]     = y[nc][2] * inv1;
        ySm[(row0 + 8) * 33 + nc * 8 + 2 * t + 1] = y[nc][3] * inv1;
    }
    __syncthreads();

    // epilogue: 2 threads per query row, f32x2 over 16 channel pairs each
    {
        const int row  = tid >> 1;
        const int half = tid & 1;
        const int n = n0b + row;
        ull yv2[32];
        #pragma unroll
        for (int i = 0; i < 32; ++i) {
            float v = ySm[row * 33 + i];
            yv2[i] = pk2(v, v);
        }
        const ull* wo2 = (const ull*)(SM + WOo);
        #pragma unroll 4
        for (int pp = 0; pp < 16; ++pp) {
            const int p = half * 16 + pp;
            ull acc = pk2(b_out[2 * p], b_out[2 * p + 1]);
            #pragma unroll
            for (int ci = 0; ci < 32; ++ci)
                acc = fma2(yv2[ci], wo2[p * 33 + ci], acc);
            float lo, hi; upk2(acc, lo, hi);
            const size_t o0 = ((size_t)(b * CC + 2 * p)) * NN + n;
            out[o0]      = lo + x[o0];
            out[o0 + NN] = hi + x[o0 + NN];
        }
    }
}

// ---------------------------------------------------------------------------
extern "C" void kernel_launch(void* const* d_in, const int* in_sizes, int n_in,
                              void* d_out, int out_size)
{
    const float* x  = (const float*)d_in[0];
    const float* wt = (const float*)d_in[1];
    const float* bt = (const float*)d_in[2];
    const float* wp = (const float*)d_in[3];
    const float* bp = (const float*)d_in[4];
    const float* wg = (const float*)d_in[5];
    const float* bg = (const float*)d_in[6];
    const float* wo = (const float*)d_in[7];
    const float* bo = (const float*)d_in[8];
    float* out = (float*)d_out;

    proj_kernel<<<dim3(NN / 64, BB), 256>>>(x, wt, bt, wp, bp, wg, bg);
    attn_kernel<<<dim3(NN / 128, BB), 256>>>(x, wo, bo, out);
}

// round 9
// speedup vs baseline: 1.3571x; 1.3571x over previous
#include <cuda_runtime.h>
#include <cuda_fp16.h>
#include <cuda_bf16.h>

// ---------------------------------------------------------------------------
// NonlocalBlock: B=4, C=64, N=9216, Ci=32, M=4608
// Round 9: R7 structure (4 fat warps x 32 rows, 128-row blocks) with single
// fp16 theta (no hi/lo split): S MMAs halved, 3 blocks/SM.
// ---------------------------------------------------------------------------

#define BB 4
#define CC 64
#define NN 9216
#define CI 32
#define MM 4608
#define TILES (MM / 64)
#define LOG2E 1.4426950408889634f

typedef unsigned long long ull;

// scratch (__device__ globals: allocation-free rule)
__device__ __half d_th[(size_t)BB * NN * CI];    // theta*log2e (fp16 rn)
__device__ __half d_ph[(size_t)BB * MM * CI];    // phi (fp16 rn)
__device__ __half d_gT[(size_t)BB * CI * MM];    // g transposed (fp16 rn)

// ---- f32x2 helpers --------------------------------------------------------
__device__ __forceinline__ ull pk2(float lo, float hi) {
    ull r; asm("mov.b64 %0, {%1,%2};" : "=l"(r) : "f"(lo), "f"(hi)); return r;
}
__device__ __forceinline__ void upk2(ull a, float& lo, float& hi) {
    asm("mov.b64 {%0,%1}, %2;" : "=f"(lo), "=f"(hi) : "l"(a));
}
__device__ __forceinline__ ull fma2(ull a, ull b, ull c) {
    ull d; asm("fma.rn.f32x2 %0, %1, %2, %3;" : "=l"(d) : "l"(a), "l"(b), "l"(c)); return d;
}

// ---- fp16 mma helpers -----------------------------------------------------
__device__ __forceinline__ void mma16(float* c, const unsigned* a,
                                      unsigned b0, unsigned b1) {
    asm volatile(
        "mma.sync.aligned.m16n8k16.row.col.f32.f16.f16.f32 "
        "{%0,%1,%2,%3}, {%4,%5,%6,%7}, {%8,%9}, {%0,%1,%2,%3};"
        : "+f"(c[0]), "+f"(c[1]), "+f"(c[2]), "+f"(c[3])
        : "r"(a[0]), "r"(a[1]), "r"(a[2]), "r"(a[3]), "r"(b0), "r"(b1));
}
__device__ __forceinline__ void mma16z(float* d, const unsigned* a,
                                       unsigned b0, unsigned b1) {
    asm volatile(
        "mma.sync.aligned.m16n8k16.row.col.f32.f16.f16.f32 "
        "{%0,%1,%2,%3}, {%4,%5,%6,%7}, {%8,%9}, {%10,%11,%12,%13};"
        : "=f"(d[0]), "=f"(d[1]), "=f"(d[2]), "=f"(d[3])
        : "r"(a[0]), "r"(a[1]), "r"(a[2]), "r"(a[3]), "r"(b0), "r"(b1),
          "f"(0.f), "f"(0.f), "f"(0.f), "f"(0.f));
}
__device__ __forceinline__ uint4 ldsm4(unsigned a) {
    uint4 r;
    asm volatile("ldmatrix.sync.aligned.m8n8.x4.shared.b16 {%0,%1,%2,%3}, [%4];"
                 : "=r"(r.x), "=r"(r.y), "=r"(r.z), "=r"(r.w) : "r"(a));
    return r;
}
__device__ __forceinline__ void cpa16(unsigned s, const void* g) {
    asm volatile("cp.async.ca.shared.global [%0], [%1], 16;" :: "r"(s), "l"(g));
}
__device__ __forceinline__ void cpcommit() { asm volatile("cp.async.commit_group;"); }
template <int N> __device__ __forceinline__ void cpwait() {
    asm volatile("cp.async.wait_group %0;" :: "n"(N));
}
__device__ __forceinline__ unsigned pkhf2(float lo, float hi) {
    unsigned d; asm("cvt.rn.f16x2.f32 %0, %1, %2;" : "=r"(d) : "f"(hi), "f"(lo));
    return d;
}
__device__ __forceinline__ unsigned h2ex2(unsigned x) {
    unsigned d; asm("ex2.approx.f16x2 %0, %1;" : "=r"(d) : "r"(x));
    return d;
}

// ---------------------------------------------------------------------------
// Kernel 1: projections + maxpool, f32x2-packed math.
// grid = (NN/64, BB), 256 threads (8 groups of 8 positions; lane = ci).
// ---------------------------------------------------------------------------
__global__ __launch_bounds__(256, 2)
void proj_kernel(const float* __restrict__ x,
                 const float* __restrict__ wt, const float* __restrict__ bt,
                 const float* __restrict__ wp, const float* __restrict__ bp,
                 const float* __restrict__ wg, const float* __restrict__ bg)
{
    __shared__ float xs[64][66];          // [chan][pos], conflict-free
    __shared__ float wts[64][32];
    __shared__ float wps[64][32];
    __shared__ float wgs[64][32];
    __shared__ __half gs[32][36];         // pooled g transpose buffer

    const int b  = blockIdx.y;
    const int n0 = blockIdx.x * 64;
    const int tid = threadIdx.x;

    for (int i = tid; i < CI * CC; i += 256) {
        int ci = i >> 6, c = i & 63;
        wts[c][ci] = wt[i];
        wps[c][ci] = wp[i];
        wgs[c][ci] = wg[i];
    }
    for (int i = tid; i < 64 * 64; i += 256) {
        int c = i >> 6, nl = i & 63;
        xs[c][nl] = x[((size_t)(b * CC + c)) * NN + n0 + nl];
    }
    __syncthreads();

    const int ci = tid & 31;
    const int g8 = tid >> 5;
    const int p0 = g8 * 8;

    ull at2[4], ap2[4], ag2[4];
    #pragma unroll
    for (int j = 0; j < 4; ++j) { at2[j] = 0ull; ap2[j] = 0ull; ag2[j] = 0ull; }

    #pragma unroll
    for (int cb = 0; cb < 64; cb += 8) {
        ull wt2[8], wp2[8], wg2[8];
        #pragma unroll
        for (int k = 0; k < 8; ++k) {
            float a = wts[cb + k][ci]; wt2[k] = pk2(a, a);
            float p = wps[cb + k][ci]; wp2[k] = pk2(p, p);
            float g = wgs[cb + k][ci]; wg2[k] = pk2(g, g);
        }
        #pragma unroll
        for (int k = 0; k < 8; ++k) {
            #pragma unroll
            for (int j = 0; j < 4; ++j) {
                ull xv = *(const ull*)&xs[cb + k][p0 + 2 * j];
                at2[j] = fma2(xv, wt2[k], at2[j]);
                ap2[j] = fma2(xv, wp2[k], ap2[j]);
                ag2[j] = fma2(xv, wg2[k], ag2[j]);
            }
        }
    }

    const float bth = bt[ci], bph = bp[ci], bgg = bg[ci];
    #pragma unroll
    for (int j = 0; j < 4; ++j) {
        const int n = n0 + p0 + 2 * j;
        float alo, ahi; upk2(at2[j], alo, ahi);
        {
            const size_t t0 = ((size_t)(b * NN + n)) * CI + ci;
            d_th[t0]      = __float2half_rn((alo + bth) * LOG2E);
            d_th[t0 + CI] = __float2half_rn((ahi + bth) * LOG2E);
        }
        float plo, phi_; upk2(ap2[j], plo, phi_);
        const int m = n >> 1;
        d_ph[((size_t)(b * MM + m)) * CI + ci] =
            __float2half_rn(fmaxf(plo, phi_) + bph);
        float glo, ghi; upk2(ag2[j], glo, ghi);
        gs[ci][g8 * 4 + j] = __float2half_rn(fmaxf(glo, ghi) + bgg);
    }
    __syncthreads();

    // coalesced gT write: 32 ci rows x 32 m (64B per row)
    for (int i = tid; i < 32 * 32; i += 256) {
        const int cr = i >> 5, ml = i & 31;
        d_gT[((size_t)(b * CI + cr)) * MM + (n0 >> 1) + ml] = gs[cr][ml];
    }
}

// ---------------------------------------------------------------------------
// smem byte offsets
// ---------------------------------------------------------------------------
#define PH0o 0u           // phi buf0: 64 keys x 80B rows = 5120
#define PH1o 5120u
#define G0o  10240u       // gT buf0: 32 ci x 144B rows = 4608
#define G1o  14848u
#define WOo  19456u       // paired w_out: 32 pairs x 33 x float2 = 8448
#define SMSZ 27904u

// ---------------------------------------------------------------------------
// Kernel 2: flash attention + out-proj + residual.
// grid = (NN/128, BB), 128 threads (4 warps x 32 query rows in 2 sets).
// ---------------------------------------------------------------------------
__global__ __launch_bounds__(128, 3)
void attn_kernel(const float* __restrict__ x,
                 const float* __restrict__ w_out,
                 const float* __restrict__ b_out,
                 float* __restrict__ out)
{
    __shared__ __align__(16) unsigned char SM[SMSZ];
    const unsigned shb = (unsigned)__cvta_generic_to_shared(SM);

    const int b    = blockIdx.y;
    const int n0b  = blockIdx.x * 128;
    const int tid  = threadIdx.x;
    const int warp = tid >> 5;
    const int lane = tid & 31;
    const int grp  = lane >> 2;
    const int t    = lane & 3;

    // w_out in channel-paired layout for f32x2 epilogue
    {
        float* woF = (float*)(SM + WOo);
        for (int i = tid; i < CC * CI; i += 128) {
            int c = i >> 5, ci = i & 31;
            woF[((c >> 1) * 33 + ci) * 2 + (c & 1)] = w_out[i];
        }
    }

    // ---- theta A fragments: two 16-row sets per warp --------------------
    const int r0 = warp * 32 + grp;        // set0 rows r0, r0+8
    const int r1 = r0 + 16;                // set1 rows r1, r1+8
    unsigned aH0[2][4], aH1[2][4];
    {
        const __half* th = d_th + ((size_t)(b * NN + n0b)) * CI;
        #pragma unroll
        for (int ch = 0; ch < 2; ++ch) {
            const int c0 = ch * 16 + 2 * t;
            aH0[ch][0] = *(const unsigned*)(th + (size_t)r0 * CI + c0);
            aH0[ch][1] = *(const unsigned*)(th + (size_t)(r0 + 8) * CI + c0);
            aH0[ch][2] = *(const unsigned*)(th + (size_t)r0 * CI + c0 + 8);
            aH0[ch][3] = *(const unsigned*)(th + (size_t)(r0 + 8) * CI + c0 + 8);
            aH1[ch][0] = *(const unsigned*)(th + (size_t)r1 * CI + c0);
            aH1[ch][1] = *(const unsigned*)(th + (size_t)(r1 + 8) * CI + c0);
            aH1[ch][2] = *(const unsigned*)(th + (size_t)r1 * CI + c0 + 8);
            aH1[ch][3] = *(const unsigned*)(th + (size_t)(r1 + 8) * CI + c0 + 8);
        }
    }

    float y0[4][4], y1[4][4];
    #pragma unroll
    for (int i = 0; i < 4; ++i)
        #pragma unroll
        for (int j = 0; j < 4; ++j) { y0[i][j] = 0.f; y1[i][j] = 0.f; }
    float y5_0[4] = {0.f, 0.f, 0.f, 0.f};
    float y5_1[4] = {0.f, 0.f, 0.f, 0.f};
    float rm00 = -1e30f, rm01 = -1e30f, rm10 = -1e30f, rm11 = -1e30f;

    const unsigned onesB = (grp == 0) ? 0x3C003C00u : 0u;

    const char* gph = (const char*)(d_ph + ((size_t)b * MM) * CI);
    const char* ggT = (const char*)(d_gT + (size_t)b * CI * MM);

    auto copy_tile = [&](int mt, int buf) {
        const unsigned phO = buf ? PH1o : PH0o;
        const unsigned gO  = buf ? G1o : G0o;
        const char* ph = gph + (size_t)mt * 64 * CI * 2;
        #pragma unroll
        for (int it = 0; it < 2; ++it) {
            int idx = tid + it * 128;          // 0..255
            int key = idx >> 2, c = idx & 3;
            cpa16(shb + phO + key * 80 + c * 16, ph + idx * 16);
        }
        #pragma unroll
        for (int it = 0; it < 2; ++it) {
            int idx = tid + it * 128;          // 0..255
            int ci = idx >> 3, c = idx & 7;
            cpa16(shb + gO + ci * 144 + c * 16,
                  ggT + (size_t)ci * (MM * 2) + (size_t)mt * 128 + c * 16);
        }
    };

    copy_tile(0, 0);
    cpcommit();

    const unsigned lmBase = (lane & 7) * 80 + (lane >> 3) * 16;   // phi ldsm
    const unsigned lmG = (unsigned)(((lane >> 4) * 8 + (lane & 7)) * 144 +
                                    ((lane >> 3) & 1) * 16);

    for (int mt = 0; mt < TILES; ++mt) {
        const int cur = mt & 1;
        if (mt + 1 < TILES) { copy_tile(mt + 1, cur ^ 1); cpcommit(); cpwait<1>(); }
        else                { cpwait<0>(); }
        __syncthreads();

        const unsigned phA = shb + (cur ? PH1o : PH0o) + lmBase;
        const unsigned gA  = shb + (cur ? G1o : G0o) + lmG;

        // phi fragments once per tile, reused by both row sets
        uint4 bh[8];
        #pragma unroll
        for (int nt = 0; nt < 8; ++nt) bh[nt] = ldsm4(phA + nt * 640);

        unsigned pa0[4][4], pa1[4][4];
        float s[8][4];

        // ================= row set 0: S + softmax ========================
        #pragma unroll
        for (int nt = 0; nt < 8; ++nt) {
            mma16z(s[nt], aH0[0], bh[nt].x, bh[nt].y);
            mma16(s[nt], aH0[1], bh[nt].z, bh[nt].w);
        }
        {
            float m0 = s[0][0], m1 = s[0][2];
            #pragma unroll
            for (int nt = 0; nt < 8; ++nt) {
                m0 = fmaxf(m0, fmaxf(s[nt][0], s[nt][1]));
                m1 = fmaxf(m1, fmaxf(s[nt][2], s[nt][3]));
            }
            m0 = fmaxf(m0, __shfl_xor_sync(0xffffffffu, m0, 1));
            m0 = fmaxf(m0, __shfl_xor_sync(0xffffffffu, m0, 2));
            m1 = fmaxf(m1, __shfl_xor_sync(0xffffffffu, m1, 1));
            m1 = fmaxf(m1, __shfl_xor_sync(0xffffffffu, m1, 2));
            const float nm0 = fmaxf(rm00, m0);
            const float nm1 = fmaxf(rm01, m1);
            const float sc0 = exp2f(rm00 - nm0);
            const float sc1 = exp2f(rm01 - nm1);
            rm00 = nm0; rm01 = nm1;
            #pragma unroll
            for (int nc = 0; nc < 4; ++nc) {
                y0[nc][0] *= sc0; y0[nc][1] *= sc0;
                y0[nc][2] *= sc1; y0[nc][3] *= sc1;
            }
            y5_0[0] *= sc0; y5_0[2] *= sc1;
            #pragma unroll
            for (int kc = 0; kc < 4; ++kc) {
                const int n0t = 2 * kc, n1t = 2 * kc + 1;
                pa0[kc][0] = h2ex2(pkhf2(s[n0t][0] - nm0, s[n0t][1] - nm0));
                pa0[kc][1] = h2ex2(pkhf2(s[n0t][2] - nm1, s[n0t][3] - nm1));
                pa0[kc][2] = h2ex2(pkhf2(s[n1t][0] - nm0, s[n1t][1] - nm0));
                pa0[kc][3] = h2ex2(pkhf2(s[n1t][2] - nm1, s[n1t][3] - nm1));
            }
        }

        // ================= row set 1: S + softmax ========================
        #pragma unroll
        for (int nt = 0; nt < 8; ++nt) {
            mma16z(s[nt], aH1[0], bh[nt].x, bh[nt].y);
            mma16(s[nt], aH1[1], bh[nt].z, bh[nt].w);
        }
        {
            float m0 = s[0][0], m1 = s[0][2];
            #pragma unroll
            for (int nt = 0; nt < 8; ++nt) {
                m0 = fmaxf(m0, fmaxf(s[nt][0], s[nt][1]));
                m1 = fmaxf(m1, fmaxf(s[nt][2], s[nt][3]));
            }
            m0 = fmaxf(m0, __shfl_xor_sync(0xffffffffu, m0, 1));
            m0 = fmaxf(m0, __shfl_xor_sync(0xffffffffu, m0, 2));
            m1 = fmaxf(m1, __shfl_xor_sync(0xffffffffu, m1, 1));
            m1 = fmaxf(m1, __shfl_xor_sync(0xffffffffu, m1, 2));
            const float nm0 = fmaxf(rm10, m0);
            const float nm1 = fmaxf(rm11, m1);
            const float sc0 = exp2f(rm10 - nm0);
            const float sc1 = exp2f(rm11 - nm1);
            rm10 = nm0; rm11 = nm1;
            #pragma unroll
            for (int nc = 0; nc < 4; ++nc) {
                y1[nc][0] *= sc0; y1[nc][1] *= sc0;
                y1[nc][2] *= sc1; y1[nc][3] *= sc1;
            }
            y5_1[0] *= sc0; y5_1[2] *= sc1;
            #pragma unroll
            for (int kc = 0; kc < 4; ++kc) {
                const int n0t = 2 * kc, n1t = 2 * kc + 1;
                pa1[kc][0] = h2ex2(pkhf2(s[n0t][0] - nm0, s[n0t][1] - nm0));
                pa1[kc][1] = h2ex2(pkhf2(s[n0t][2] - nm1, s[n0t][3] - nm1));
                pa1[kc][2] = h2ex2(pkhf2(s[n1t][0] - nm0, s[n1t][1] - nm0));
                pa1[kc][3] = h2ex2(pkhf2(s[n1t][2] - nm1, s[n1t][3] - nm1));
            }
        }

        // ================= P @ g (both sets share g frags) ===============
        #pragma unroll
        for (int kc = 0; kc < 4; ++kc) {
            uint4 h0 = ldsm4(gA + kc * 32);            // nc 0,1
            uint4 h1 = ldsm4(gA + 2304 + kc * 32);     // nc 2,3
            mma16(y0[0], pa0[kc], h0.x, h0.y);
            mma16(y0[1], pa0[kc], h0.z, h0.w);
            mma16(y0[2], pa0[kc], h1.x, h1.y);
            mma16(y0[3], pa0[kc], h1.z, h1.w);
            mma16(y1[0], pa1[kc], h0.x, h0.y);
            mma16(y1[1], pa1[kc], h0.z, h0.w);
            mma16(y1[2], pa1[kc], h1.x, h1.y);
            mma16(y1[3], pa1[kc], h1.z, h1.w);
            mma16(y5_0, pa0[kc], onesB, onesB);
            mma16(y5_1, pa1[kc], onesB, onesB);
        }
        __syncthreads();
    }

    // row sums: col 0 lives on t==0 lanes of each group
    const float rs00 = __shfl_sync(0xffffffffu, y5_0[0], lane & ~3);
    const float rs01 = __shfl_sync(0xffffffffu, y5_0[2], lane & ~3);
    const float rs10 = __shfl_sync(0xffffffffu, y5_1[0], lane & ~3);
    const float rs11 = __shfl_sync(0xffffffffu, y5_1[2], lane & ~3);
    const float i00 = 1.0f / rs00, i01 = 1.0f / rs01;
    const float i10 = 1.0f / rs10, i11 = 1.0f / rs11;

    float* ySm = (float*)SM;               // 128 x 33 floats = 16896 B < WOo
    #pragma unroll
    for (int nc = 0; nc < 4; ++nc) {
        ySm[r0 * 33 + nc * 8 + 2 * t]            = y0[nc][0] * i00;
        ySm[r0 * 33 + nc * 8 + 2 * t + 1]        = y0[nc][1] * i00;
        ySm[(r0 + 8) * 33 + nc * 8 + 2 * t]      = y0[nc][2] * i01;
        ySm[(r0 + 8) * 33 + nc * 8 + 2 * t + 1]  = y0[nc][3] * i01;
        ySm[r1 * 33 + nc * 8 + 2 * t]            = y1[nc][0] * i10;
        ySm[r1 * 33 + nc * 8 + 2 * t + 1]        = y1[nc][1] * i10;
        ySm[(r1 + 8) * 33 + nc * 8 + 2 * t]      = y1[nc][2] * i11;
        ySm[(r1 + 8) * 33 + nc * 8 + 2 * t + 1]  = y1[nc][3] * i11;
    }
    __syncthreads();

    // epilogue: one thread per query row, f32x2 over channel pairs
    {
        const int row = tid;
        const int n = n0b + row;
        ull yv2[32];
        #pragma unroll
        for (int i = 0; i < 32; ++i) {
            float v = ySm[row * 33 + i];
            yv2[i] = pk2(v, v);
        }
        const ull* wo2 = (const ull*)(SM + WOo);
        #pragma unroll 4
        for (int p = 0; p < 32; ++p) {
            ull acc = pk2(b_out[2 * p], b_out[2 * p + 1]);
            #pragma unroll
            for (int ci = 0; ci < 32; ++ci)
                acc = fma2(yv2[ci], wo2[p * 33 + ci], acc);
            float lo, hi; upk2(acc, lo, hi);
            const size_t o0 = ((size_t)(b * CC + 2 * p)) * NN + n;
            out[o0]      = lo + x[o0];
            out[o0 + NN] = hi + x[o0 + NN];
        }
    }
}

// ---------------------------------------------------------------------------
extern "C" void kernel_launch(void* const* d_in, const int* in_sizes, int n_in,
                              void* d_out, int out_size)
{
    const float* x  = (const float*)d_in[0];
    const float* wt = (const float*)d_in[1];
    const float* bt = (const float*)d_in[2];
    const float* wp = (const float*)d_in[3];
    const float* bp = (const float*)d_in[4];
    const float* wg = (const float*)d_in[5];
    const float* bg = (const float*)d_in[6];
    const float* wo = (const float*)d_in[7];
    const float* bo = (const float*)d_in[8];
    float* out = (float*)d_out;

    proj_kernel<<<dim3(NN / 64, BB), 256>>>(x, wt, bt, wp, bp, wg, bg);
    attn_kernel<<<dim3(NN / 128, BB), 128>>>(x, wo, bo, out);
}